// round 5
// baseline (speedup 1.0000x reference)
#include <cuda_runtime.h>
#include <math_constants.h>
#include <cstdint>

#define Bn 16
#define Kn 256
#define Zn 128
#define Hn 128
#define BK (Bn*Kn)

typedef unsigned long long ull;

// ---------------- device scratch ----------------
__device__ __align__(16) float g_W1t[Zn*Zn];       // W1^T : [k][c_out]
__device__ __align__(16) float g_W2t[Zn*Zn];
__device__ __align__(16) float g_Wut[2*Zn*Hn];     // Wu^T : [k][h]
__device__ __align__(16) float g_m1z[BK*Zn];
__device__ __align__(16) float g_m2z[BK*Zn];
__device__ __align__(16) float g_m[BK*Zn];
__device__ __align__(16) unsigned g_nib[Bn*64*Kn]; // [b][g][i] = (g*16+idx)*32

// ---------------- helpers ----------------
__device__ __forceinline__ ull ffma2(ull a, ull b, ull c) {
    ull d;
    asm("fma.rn.f32x2 %0, %1, %2, %3;" : "=l"(d) : "l"(a), "l"(b), "l"(c));
    return d;
}
__device__ __forceinline__ ull pack2(float lo, float hi) {
    ull d;
    asm("mov.b64 %0, {%1, %2};" : "=l"(d) : "f"(lo), "f"(hi));
    return d;
}
__device__ __forceinline__ float2 unpack2(ull v) {
    float2 r;
    asm("mov.b64 {%0, %1}, %2;" : "=f"(r.x), "=f"(r.y) : "l"(v));
    return r;
}
__device__ __forceinline__ uint32_t smem_u32(const void* p) {
    uint32_t a;
    asm("{ .reg .u64 t; cvta.to.shared.u64 t, %1; cvt.u32.u64 %0, t; }" : "=r"(a) : "l"(p));
    return a;
}
__device__ __forceinline__ void cpasync16(uint32_t dst, const void* src) {
    asm volatile("cp.async.cg.shared.global [%0], [%1], 16;" :: "r"(dst), "l"(src) : "memory");
}
#define CP_COMMIT() asm volatile("cp.async.commit_group;" ::: "memory")
#define WAITG(n)    asm volatile("cp.async.wait_group %0;" :: "n"(n) : "memory")
__device__ __forceinline__ void wait_chunk(int ch) {
    switch (ch) {
        case 0: WAITG(3); break;
        case 1: WAITG(2); break;
        case 2: WAITG(1); break;
        default: WAITG(0); break;
    }
}

// =========================================================================
// prep: transpose weights + build nibble table offsets
// g_nib[b][g][i] = (g*16 + idx)*32, idx bit t = (P[b][4g+t][i] != 0)
// =========================================================================
__global__ void prep_kernel(const float* __restrict__ W1,
                            const float* __restrict__ W2,
                            const float* __restrict__ Wu,
                            const int* __restrict__ P) {
    int stride = gridDim.x * blockDim.x;
    int t0 = blockIdx.x * blockDim.x + threadIdx.x;
    for (int idx = t0; idx < Zn * Zn; idx += stride) {
        int k = idx / Zn, c = idx % Zn;
        g_W1t[idx] = W1[c * Zn + k];
        g_W2t[idx] = W2[c * Zn + k];
    }
    for (int idx = t0; idx < 2 * Zn * Hn; idx += stride) {
        int k = idx / Hn, h = idx % Hn;
        g_Wut[idx] = Wu[h * (2 * Zn) + k];
    }
    const int total = Bn * 64 * Kn;
    for (int e = t0; e < total; e += stride) {
        int i = e & 255;
        int g = (e >> 8) & 63;
        int b = e >> 14;
        const int* p = P + ((size_t)(b * Kn + 4 * g)) * Kn + i;
        int idx = (p[0] != 0) | ((p[Kn] != 0) << 1) |
                  ((p[2 * Kn] != 0) << 2) | ((p[3 * Kn] != 0) << 3);
        g_nib[(b * 64 + g) * Kn + i] = (unsigned)((g * 16 + idx) * 32);
    }
}

// =========================================================================
// K1: m1z or m2z = z @ W^T + b. Block 32m x 128n, full K=128 resident.
// Grid (128, 2): y selects matrix. smem = Xs[128][68] + Ws[128][128] = 100KB
// -> 2 blocks/SM.
// =========================================================================
#define L12_SMEM (128*68*4 + 128*128*4)
__global__ __launch_bounds__(256, 2)
void linear12_kernel(const float* __restrict__ z,
                     const float* __restrict__ b1,
                     const float* __restrict__ b2) {
    extern __shared__ float sm[];
    float* Xs = sm;                 // [128][68] dup-pairs
    float* Ws = sm + 128 * 68;      // [128][128]
    const uint32_t Ws_a = smem_u32(Ws);

    const int tid = threadIdx.x;
    const int r0  = blockIdx.x * 32;
    const int wsel = blockIdx.y;
    const float* __restrict__ W    = wsel ? g_W2t : g_W1t;
    const float* __restrict__ bias = wsel ? b2 : b1;
    float* __restrict__ outp       = wsel ? g_m2z : g_m1z;

    // async weight panel, 4 k-chunk groups of 32
#pragma unroll
    for (int ch = 0; ch < 4; ch++) {
#pragma unroll
        for (int i = 0; i < 4; i++) {
            int e = tid + i * 256;           // 1024 f4 units per chunk
            int kk = e >> 5, c4 = (e & 31) * 4;
            int off = (ch * 32 + kk) * 128 + c4;
            cpasync16(Ws_a + (uint32_t)off * 4u, W + off);
        }
        CP_COMMIT();
    }

    // z tile -> dup pairs
    {
        int xr = tid >> 3;
        int xc = (tid & 7) * 4;
#pragma unroll
        for (int ch = 0; ch < 4; ch++) {
            float4 v = *reinterpret_cast<const float4*>(
                &z[(size_t)(r0 + xr) * Zn + ch * 32 + xc]);
            float vv[4] = {v.x, v.y, v.z, v.w};
#pragma unroll
            for (int j = 0; j < 4; j++)
                *reinterpret_cast<ull*>(&Xs[(ch * 32 + xc + j) * 68 + xr * 2]) =
                    pack2(vv[j], vv[j]);
        }
    }

    const int lane = tid & 31, w = tid >> 5;
    const int mbase = (w >> 2) * 16 + (lane >> 3) * 4;
    const int nbase = (w & 3) * 32 + (lane & 7) * 4;

    ull acc[4][2];
#pragma unroll
    for (int m = 0; m < 4; m++) { acc[m][0] = 0ull; acc[m][1] = 0ull; }

    for (int ch = 0; ch < 4; ch++) {
        wait_chunk(ch);
        __syncthreads();
#pragma unroll 8
        for (int kk = ch * 32; kk < ch * 32 + 32; kk++) {
            ulonglong2 a01 = *reinterpret_cast<const ulonglong2*>(&Xs[kk * 68 + mbase * 2]);
            ulonglong2 a23 = *reinterpret_cast<const ulonglong2*>(&Xs[kk * 68 + mbase * 2 + 4]);
            ulonglong2 bw  = *reinterpret_cast<const ulonglong2*>(&Ws[kk * 128 + nbase]);
            ull av[4] = {a01.x, a01.y, a23.x, a23.y};
#pragma unroll
            for (int m = 0; m < 4; m++) {
                acc[m][0] = ffma2(av[m], bw.x, acc[m][0]);
                acc[m][1] = ffma2(av[m], bw.y, acc[m][1]);
            }
        }
    }

    float4 bb = *reinterpret_cast<const float4*>(&bias[nbase]);
#pragma unroll
    for (int m = 0; m < 4; m++) {
        float2 lo = unpack2(acc[m][0]);
        float2 hi = unpack2(acc[m][1]);
        float4 o = {lo.x + bb.x, lo.y + bb.y, hi.x + bb.z, hi.y + bb.w};
        *reinterpret_cast<float4*>(&outp[(size_t)(r0 + mbase + m) * Zn + nbase]) = o;
    }
}

// =========================================================================
// K2: four-Russians masked max.
// m[b,i,c] = relu(m1z[b,i,c] + max_{j: P[b,j,i]!=0} m2z[b,j,c])
// Block = (b, i-half 128, c-chunk 32), 512 threads.
// smem: tab[64g][16s][32c] 128KB + m2s[256][32] 32KB + nibS[128][68] 34KB
// Inner: acc = fmax(acc, tab[nib(i,g) + lane])  (table offset precomputed)
// =========================================================================
#define MM_SMEM (64*16*32*4 + 256*32*4 + 128*68*4)
__global__ __launch_bounds__(512, 1)
void maxmsg_kernel() {
    extern __shared__ float sm[];
    float* tab = sm;                                    // 32768 floats
    float* m2s = sm + 64 * 16 * 32;                     // 8192 floats
    unsigned* nibS = reinterpret_cast<unsigned*>(m2s + 256 * 32); // [128][68]
    const uint32_t m2s_a = smem_u32(m2s);

    const int tid = threadIdx.x;
    const int b      = blockIdx.y;
    const int cchunk = blockIdx.x & 3;
    const int ihalf  = blockIdx.x >> 2;
    const int c0 = cchunk * 32;
    const int i0 = ihalf * 128;

    // stage m2z[b][0..255][c0..c0+31]
    const float* m2base = g_m2z + (size_t)b * Kn * Zn + c0;
#pragma unroll
    for (int i = 0; i < 4; i++) {
        int e = tid + i * 512;              // 2048 f4 units
        int jj = e >> 3, c4 = (e & 7) * 4;
        cpasync16(m2s_a + (uint32_t)(jj * 32 + c4) * 4u,
                  m2base + (size_t)jj * Zn + c4);
    }
    CP_COMMIT();

    // stage nibble offsets: nibS[i_local][g] <- g_nib[b][g][i0+i_local]
#pragma unroll
    for (int it = 0; it < 16; it++) {
        int e = tid + it * 512;             // 8192
        int g = e >> 7, il = e & 127;
        nibS[il * 68 + g] = g_nib[(b * 64 + g) * Kn + i0 + il];
    }

    WAITG(0);
    __syncthreads();

    // build table: unit = (g, c); 16 subsets each
    {
        const int c = tid & 31;
#pragma unroll
        for (int u = 0; u < 4; u++) {
            int g = u * 16 + (tid >> 5);
            const float* row = &m2s[4 * g * 32 + c];
            float e0 = row[0], e1 = row[32], e2 = row[64], e3 = row[96];
            float t3 = fmaxf(e0, e1);
            float t5 = fmaxf(e0, e2), t6 = fmaxf(e1, e2), t7 = fmaxf(t3, e2);
            float* tb = &tab[g * 16 * 32 + c];
            tb[0*32] = -CUDART_INF_F;
            tb[1*32] = e0;  tb[2*32] = e1;  tb[3*32] = t3;
            tb[4*32] = e2;  tb[5*32] = t5;  tb[6*32] = t6;  tb[7*32] = t7;
            tb[8*32]  = e3;
            tb[9*32]  = fmaxf(e0, e3);
            tb[10*32] = fmaxf(e1, e3);
            tb[11*32] = fmaxf(t3, e3);
            tb[12*32] = fmaxf(e2, e3);
            tb[13*32] = fmaxf(t5, e3);
            tb[14*32] = fmaxf(t6, e3);
            tb[15*32] = fmaxf(t7, e3);
        }
    }
    __syncthreads();

    // main loop: warp w handles 8 i's, lanes = 32 c
    const int lane = tid & 31, w = tid >> 5;
    const int wbase = w * 8;
    const float* tabL = tab + lane;

    float acc[8];
#pragma unroll
    for (int ii = 0; ii < 8; ii++) acc[ii] = -CUDART_INF_F;

    for (int g4 = 0; g4 < 16; g4++) {
        uint4 nv[8];
#pragma unroll
        for (int ii = 0; ii < 8; ii++)
            nv[ii] = *reinterpret_cast<const uint4*>(&nibS[(wbase + ii) * 68 + g4 * 4]);
#pragma unroll
        for (int ii = 0; ii < 8; ii++) acc[ii] = fmaxf(acc[ii], tabL[nv[ii].x]);
#pragma unroll
        for (int ii = 0; ii < 8; ii++) acc[ii] = fmaxf(acc[ii], tabL[nv[ii].y]);
#pragma unroll
        for (int ii = 0; ii < 8; ii++) acc[ii] = fmaxf(acc[ii], tabL[nv[ii].z]);
#pragma unroll
        for (int ii = 0; ii < 8; ii++) acc[ii] = fmaxf(acc[ii], tabL[nv[ii].w]);
    }

    // epilogue
#pragma unroll
    for (int ii = 0; ii < 8; ii++) {
        int i = i0 + wbase + ii;
        size_t off = ((size_t)b * Kn + i) * Zn + c0 + lane;
        float m1 = g_m1z[off];
        g_m[off] = fmaxf(m1 + acc[ii], 0.f);
    }
}

// =========================================================================
// K3: out = relu([z, m] @ Wu^T + bu), K=256.
// Block 16m x 128n, Xs full-K dup-pairs (single buf), Ws double-buffered
// 64-k chunks. smem = Xs[256][36] + Ws[2][64][128] = 102KB -> 2 blocks/SM.
// =========================================================================
#define FIN_SMEM (256*36*4 + 2*64*128*4)
__global__ __launch_bounds__(256, 2)
void final_kernel(const float* __restrict__ z,
                  const float* __restrict__ bu,
                  float* __restrict__ out) {
    extern __shared__ float sm[];
    float* Xs = sm;                  // [256][36] dup-pairs (16 m -> 32 floats + pad)
    float* Ws = sm + 256 * 36;       // [2][64][128]
    const uint32_t Ws_a = smem_u32(Ws);

    const int tid = threadIdx.x;
    const int r0  = blockIdx.x * 16;

    auto load_w = [&](int ch, int buf) {
#pragma unroll
        for (int i = 0; i < 8; i++) {
            int e = tid + i * 256;           // 2048 f4 units
            int kk = e >> 5, c4 = (e & 31) * 4;
            cpasync16(Ws_a + (uint32_t)(buf * 8192 + kk * 128 + c4) * 4u,
                      g_Wut + (ch * 64 + kk) * 128 + c4);
        }
        CP_COMMIT();
    };
    load_w(0, 0);
    load_w(1, 1);

    // Xs: [z | m] dup pairs, full K=256
    {
        int xr = tid >> 4;              // 0..15
        int xc4 = (tid & 15) * 4;       // 0..60
#pragma unroll
        for (int ch = 0; ch < 4; ch++) {
            int k = ch * 64 + xc4;
            const float* src = (k < Zn)
                ? &z[(size_t)(r0 + xr) * Zn + k]
                : &g_m[(size_t)(r0 + xr) * Zn + (k - Zn)];
            float4 v = *reinterpret_cast<const float4*>(src);
            float vv[4] = {v.x, v.y, v.z, v.w};
#pragma unroll
            for (int j = 0; j < 4; j++)
                *reinterpret_cast<ull*>(&Xs[(k + j) * 36 + xr * 2]) =
                    pack2(vv[j], vv[j]);
        }
    }

    const int lane = tid & 31, w = tid >> 5;
    const int mwarp = w >> 2, nwarp = w & 3;
    const int m0 = mwarp * 8 + (lane >> 3) * 2;      // 2 consecutive m
    const int n0 = nwarp * 32 + (lane & 7) * 4;      // 4 consecutive n

    ull acc[2][2];
    acc[0][0] = acc[0][1] = acc[1][0] = acc[1][1] = 0ull;

    for (int ch = 0; ch < 4; ch++) {
        if (ch < 3) { WAITG(1); } else { WAITG(0); }
        __syncthreads();
        const float* Wb = Ws + (ch & 1) * 8192;
        const int k0 = ch * 64;
#pragma unroll 8
        for (int kk = 0; kk < 64; kk++) {
            ulonglong2 av = *reinterpret_cast<const ulonglong2*>(
                &Xs[(k0 + kk) * 36 + m0 * 2]);
            ulonglong2 bw = *reinterpret_cast<const ulonglong2*>(&Wb[kk * 128 + n0]);
            acc[0][0] = ffma2(av.x, bw.x, acc[0][0]);
            acc[0][1] = ffma2(av.x, bw.y, acc[0][1]);
            acc[1][0] = ffma2(av.y, bw.x, acc[1][0]);
            acc[1][1] = ffma2(av.y, bw.y, acc[1][1]);
        }
        __syncthreads();
        if (ch + 2 < 4) load_w(ch + 2, ch & 1);
    }

    float4 bb = *reinterpret_cast<const float4*>(&bu[n0]);
#pragma unroll
    for (int m = 0; m < 2; m++) {
        float2 lo = unpack2(acc[m][0]);
        float2 hi = unpack2(acc[m][1]);
        float4 o;
        o.x = fmaxf(lo.x + bb.x, 0.f);
        o.y = fmaxf(lo.y + bb.y, 0.f);
        o.z = fmaxf(hi.x + bb.z, 0.f);
        o.w = fmaxf(hi.y + bb.w, 0.f);
        *reinterpret_cast<float4*>(&out[(size_t)(r0 + m0 + m) * Hn + n0]) = o;
    }
}

// --------------------------------------------------------------------------
extern "C" void kernel_launch(void* const* d_in, const int* in_sizes, int n_in,
                              void* d_out, int out_size) {
    const float* z  = (const float*)d_in[0];
    const int*   P  = (const int*)  d_in[1];
    const float* W1 = (const float*)d_in[2];
    const float* b1 = (const float*)d_in[3];
    const float* W2 = (const float*)d_in[4];
    const float* b2 = (const float*)d_in[5];
    const float* Wu = (const float*)d_in[6];
    const float* bu = (const float*)d_in[7];
    float* out = (float*)d_out;

    cudaFuncSetAttribute(linear12_kernel, cudaFuncAttributeMaxDynamicSharedMemorySize, L12_SMEM);
    cudaFuncSetAttribute(maxmsg_kernel,   cudaFuncAttributeMaxDynamicSharedMemorySize, MM_SMEM);
    cudaFuncSetAttribute(final_kernel,    cudaFuncAttributeMaxDynamicSharedMemorySize, FIN_SMEM);

    prep_kernel<<<1024, 256>>>(W1, W2, Wu, P);
    linear12_kernel<<<dim3(BK / 32, 2), 256, L12_SMEM>>>(z, b1, b2);
    maxmsg_kernel<<<dim3(8, Bn), 512, MM_SMEM>>>();
    final_kernel<<<BK / 16, 256, FIN_SMEM>>>(z, bu, out);
}